// round 2
// baseline (speedup 1.0000x reference)
#include <cuda_runtime.h>
#include <math.h>

#define HID 256
#define NMAX 50000
#define EMAX 800000

// ---------------- device scratch (static: no allocations allowed) ----------
__device__ float g_Q[(size_t)NMAX * HID];
__device__ float g_K[(size_t)NMAX * HID];
__device__ float g_V[(size_t)NMAX * HID];
__device__ float g_attn[(size_t)NMAX * HID];
__device__ float g_h[(size_t)NMAX * HID];

__device__ int g_cnt[NMAX + 1];
__device__ int g_rowoff[NMAX + 1];
__device__ int g_cursor[NMAX];
__device__ int g_csrc[EMAX];
__device__ int g_blksum[64];

__device__ float g_colsum[HID];
__device__ float g_colsq[HID];

// ---------------- zero / CSR build -----------------------------------------
__global__ void zero_kernel(int n) {
    int i = blockIdx.x * blockDim.x + threadIdx.x;
    if (i <= n) g_cnt[i] = 0;
    if (i < HID) { g_colsum[i] = 0.f; g_colsq[i] = 0.f; }
}

__global__ void count_kernel(const int* __restrict__ dst, int e) {
    int i = blockIdx.x * blockDim.x + threadIdx.x;
    if (i < e) atomicAdd(&g_cnt[dst[i]], 1);
}

// block-level exclusive scan (1024-wide Hillis-Steele)
__global__ void scanA(int n) {
    __shared__ int sm[1024];
    int tid = threadIdx.x;
    int gid = blockIdx.x * 1024 + tid;
    int v = (gid < n) ? g_cnt[gid] : 0;
    sm[tid] = v;
    __syncthreads();
    for (int off = 1; off < 1024; off <<= 1) {
        int t = (tid >= off) ? sm[tid - off] : 0;
        __syncthreads();
        sm[tid] += t;
        __syncthreads();
    }
    if (gid < n) g_rowoff[gid] = sm[tid] - v;   // exclusive
    if (tid == 1023) g_blksum[blockIdx.x] = sm[1023];
}

__global__ void scanB(int nb) {
    __shared__ int sm[64];
    int tid = threadIdx.x;
    int v = (tid < nb) ? g_blksum[tid] : 0;
    sm[tid] = v;
    __syncthreads();
    for (int off = 1; off < 64; off <<= 1) {
        int t = (tid >= off) ? sm[tid - off] : 0;
        __syncthreads();
        sm[tid] += t;
        __syncthreads();
    }
    if (tid < nb) g_blksum[tid] = sm[tid] - v;  // exclusive
}

__global__ void scanC(int n, int e) {
    int gid = blockIdx.x * blockDim.x + threadIdx.x;
    if (gid < n) {
        int r = g_rowoff[gid] + g_blksum[gid >> 10];
        g_rowoff[gid] = r;
        g_cursor[gid] = r;
    }
    if (gid == 0) g_rowoff[n] = e;
}

__global__ void scatter_kernel(const int* __restrict__ src,
                               const int* __restrict__ dst, int e) {
    int i = blockIdx.x * blockDim.x + threadIdx.x;
    if (i < e) {
        int p = atomicAdd(&g_cursor[dst[i]], 1);
        g_csrc[p] = src[i];
    }
}

// ---------------- GEMM: C[M,256] = A[M,256] @ W[256,256] -------------------
// MODE 0: A = x (arg), z selects (WQ->g_Q, WK->g_K, WV->g_V)
// MODE 1: A = g_attn, W = W0 (W_out), C = g_h, epilogue += bias + resid
template <int MODE>
__global__ void __launch_bounds__(256, 2)
gemm256(const float* __restrict__ A,
        const float* __restrict__ W0,
        const float* __restrict__ W1,
        const float* __restrict__ W2,
        const float* __restrict__ bias,
        const float* __restrict__ resid,
        int M) {
    const float* Ap;
    const float* W;
    float* C;
    if (MODE == 0) {
        Ap = A;
        if (blockIdx.z == 0)      { W = W0; C = g_Q; }
        else if (blockIdx.z == 1) { W = W1; C = g_K; }
        else                      { W = W2; C = g_V; }
    } else {
        Ap = g_attn; W = W0; C = g_h;
    }

    __shared__ __align__(16) float As[8][128];   // [k][m]
    __shared__ __align__(16) float Ws[8][128];   // [k][n]

    int tid = threadIdx.x;
    int tx = tid & 15;        // col group
    int ty = tid >> 4;        // row group
    int m0 = blockIdx.y * 128;
    int n0 = blockIdx.x * 128;

    float c[8][8];
#pragma unroll
    for (int i = 0; i < 8; i++)
#pragma unroll
        for (int j = 0; j < 8; j++) c[i][j] = 0.f;

    int arow = tid >> 1;          // 0..127
    int acol = (tid & 1) * 4;     // 0 or 4
    int am = m0 + arow;
    if (am >= M) am = M - 1;      // clamp (stores are guarded)
    int wr = tid >> 5;            // 0..7
    int wc = (tid & 31) * 4;      // 0..124

    for (int k0 = 0; k0 < HID; k0 += 8) {
        float4 av = *(const float4*)(Ap + (size_t)am * HID + k0 + acol);
        float4 wv = *(const float4*)(W + (size_t)(k0 + wr) * HID + n0 + wc);
        __syncthreads();
        As[acol + 0][arow] = av.x;
        As[acol + 1][arow] = av.y;
        As[acol + 2][arow] = av.z;
        As[acol + 3][arow] = av.w;
        *(float4*)(&Ws[wr][wc]) = wv;
        __syncthreads();
#pragma unroll
        for (int kk = 0; kk < 8; kk++) {
            float a[8], b[8];
            *(float4*)(a)     = *(const float4*)(&As[kk][ty * 8]);
            *(float4*)(a + 4) = *(const float4*)(&As[kk][ty * 8 + 4]);
            *(float4*)(b)     = *(const float4*)(&Ws[kk][tx * 8]);
            *(float4*)(b + 4) = *(const float4*)(&Ws[kk][tx * 8 + 4]);
#pragma unroll
            for (int i = 0; i < 8; i++)
#pragma unroll
                for (int j = 0; j < 8; j++) c[i][j] += a[i] * b[j];
        }
    }

#pragma unroll
    for (int i = 0; i < 8; i++) {
        int m = m0 + ty * 8 + i;
        if (m < M) {
            int col = n0 + tx * 8;
            if (MODE == 1) {
#pragma unroll
                for (int j = 0; j < 8; j++)
                    c[i][j] += bias[col + j] + resid[(size_t)m * HID + col + j];
            }
            float4 o0 = make_float4(c[i][0], c[i][1], c[i][2], c[i][3]);
            float4 o1 = make_float4(c[i][4], c[i][5], c[i][6], c[i][7]);
            *(float4*)(C + (size_t)m * HID + col)     = o0;
            *(float4*)(C + (size_t)m * HID + col + 4) = o1;
        }
    }
}

// ---------------- attention: warp per destination node ---------------------
// lane -> dims [8*lane, 8*lane+8) ; head = lane>>2 (4 lanes per head)
__global__ void attn_kernel(int n) {
    int gw = (blockIdx.x * blockDim.x + threadIdx.x) >> 5;
    if (gw >= n) return;
    int lane = threadIdx.x & 31;

    const float* qr = g_Q + (size_t)gw * HID + lane * 8;
    float4 q0 = *(const float4*)qr;
    float4 q1 = *(const float4*)(qr + 4);

    int beg = g_rowoff[gw];
    int end = g_rowoff[gw + 1];

    float m = -INFINITY;
    float den = 0.f;
    float acc[8];
#pragma unroll
    for (int j = 0; j < 8; j++) acc[j] = 0.f;

    for (int e = beg; e < end; ++e) {
        int s = g_csrc[e];
        const float* kr = g_K + (size_t)s * HID + lane * 8;
        const float* vr = g_V + (size_t)s * HID + lane * 8;
        float4 k0 = *(const float4*)kr;
        float4 k1 = *(const float4*)(kr + 4);
        float4 v0 = *(const float4*)vr;
        float4 v1 = *(const float4*)(vr + 4);

        float p = q0.x * k0.x + q0.y * k0.y + q0.z * k0.z + q0.w * k0.w +
                  q1.x * k1.x + q1.y * k1.y + q1.z * k1.z + q1.w * k1.w;
        p += __shfl_xor_sync(0xffffffffu, p, 1);
        p += __shfl_xor_sync(0xffffffffu, p, 2);
        float sc = p * 0.17677669529663687f;   // 1/sqrt(32)

        float nm = fmaxf(m, sc);
        float cf = __expf(m - nm);             // 0 on first edge (m=-inf)
        float pf = __expf(sc - nm);
        den = den * cf + pf;
        acc[0] = acc[0] * cf + pf * v0.x;
        acc[1] = acc[1] * cf + pf * v0.y;
        acc[2] = acc[2] * cf + pf * v0.z;
        acc[3] = acc[3] * cf + pf * v0.w;
        acc[4] = acc[4] * cf + pf * v1.x;
        acc[5] = acc[5] * cf + pf * v1.y;
        acc[6] = acc[6] * cf + pf * v1.z;
        acc[7] = acc[7] * cf + pf * v1.w;
        m = nm;
    }

    float inv = (den > 0.f) ? 1.f / den : 0.f;
    float* o = g_attn + (size_t)gw * HID + lane * 8;
    float4 o0 = make_float4(acc[0] * inv, acc[1] * inv, acc[2] * inv, acc[3] * inv);
    float4 o1 = make_float4(acc[4] * inv, acc[5] * inv, acc[6] * inv, acc[7] * inv);
    *(float4*)o = o0;
    *(float4*)(o + 4) = o1;
}

// ---------------- GraphNorm stats + apply + GELU ---------------------------
__global__ void stats_kernel(int n) {
    int c = threadIdx.x;                 // 256 threads = 256 columns
    float s = 0.f, s2 = 0.f;
    for (int r = blockIdx.x; r < n; r += gridDim.x) {
        float v = g_h[(size_t)r * HID + c];
        s += v;
        s2 += v * v;
    }
    atomicAdd(&g_colsum[c], s);
    atomicAdd(&g_colsq[c], s2);
}

__global__ void norm_gelu_kernel(const float* __restrict__ gw,
                                 const float* __restrict__ gb,
                                 const float* __restrict__ gms,
                                 float* __restrict__ out, int n) {
    int c = threadIdx.x;
    float invn = 1.f / (float)n;
    float mean = g_colsum[c] * invn;
    float ex2  = g_colsq[c] * invn;
    float s = gms[c];
    // var = E[(h - s*m)^2] = E[h^2] - 2*s*m*E[h] + s^2*m^2
    float var = ex2 - 2.f * s * mean * mean + s * s * mean * mean;
    float rstd = rsqrtf(var + 1e-5f);
    float w = gw[c] * rstd;
    float b = gb[c];
    float off = s * mean;
    for (int r = blockIdx.x; r < n; r += gridDim.x) {
        float h = g_h[(size_t)r * HID + c];
        float o = (h - off) * w + b;
        out[(size_t)r * HID + c] = 0.5f * o * (1.f + erff(o * 0.70710678118654752f));
    }
}

// ---------------- launch ----------------------------------------------------
extern "C" void kernel_launch(void* const* d_in, const int* in_sizes, int n_in,
                              void* d_out, int out_size) {
    const float* x     = (const float*)d_in[0];
    const float* WQ    = (const float*)d_in[1];
    const float* WK    = (const float*)d_in[2];
    const float* WV    = (const float*)d_in[3];
    const float* W_out = (const float*)d_in[4];
    const float* b_out = (const float*)d_in[5];
    const float* gnw   = (const float*)d_in[6];
    const float* gnb   = (const float*)d_in[7];
    const float* gms   = (const float*)d_in[8];
    const int*   ei    = (const int*)d_in[9];

    int n = in_sizes[0] / HID;
    int e = in_sizes[9] / 2;
    if (n > NMAX || e > EMAX) return;

    const int* src = ei;
    const int* dst = ei + e;

    // CSR build
    zero_kernel<<<(n + 256) / 256, 256>>>(n);
    count_kernel<<<(e + 255) / 256, 256>>>(dst, e);
    int nb = (n + 1023) / 1024;
    scanA<<<nb, 1024>>>(n);
    scanB<<<1, 64>>>(nb);
    scanC<<<(n + 255) / 256, 256>>>(n, e);
    scatter_kernel<<<(e + 255) / 256, 256>>>(src, dst, e);

    // QKV projections
    dim3 gqkv(2, (n + 127) / 128, 3);
    gemm256<0><<<gqkv, 256>>>(x, WQ, WK, WV, nullptr, nullptr, n);

    // attention (warp per node)
    attn_kernel<<<(n * 32 + 255) / 256, 256>>>(n);

    // out projection + bias + residual
    dim3 gout(2, (n + 127) / 128, 1);
    gemm256<1><<<gout, 256>>>(nullptr, W_out, nullptr, nullptr, b_out, x, n);

    // GraphNorm + GELU
    stats_kernel<<<512, 256>>>(n);
    norm_gelu_kernel<<<512, 256>>>(gnw, gnb, gms, (float*)d_out, n);
}

// round 3
// speedup vs baseline: 1.0452x; 1.0452x over previous
#include <cuda_runtime.h>
#include <math.h>

#define HID 256
#define NMAX 50000
#define EMAX 800000

// ---------------- device scratch (static: no allocations allowed) ----------
__device__ float g_Q[(size_t)NMAX * HID];
__device__ float g_K[(size_t)NMAX * HID];
__device__ float g_V[(size_t)NMAX * HID];
__device__ float g_attn[(size_t)NMAX * HID];
__device__ float g_h[(size_t)NMAX * HID];

__device__ int g_cnt[NMAX + 1];
__device__ int g_rowoff[NMAX + 1];
__device__ int g_cursor[NMAX];
__device__ int g_csrc[EMAX];
__device__ int g_blksum[64];

__device__ float g_colsum[HID];
__device__ float g_colsq[HID];

// ---------------- packed f32x2 helpers (Blackwell) -------------------------
__device__ __forceinline__ void fma2(unsigned long long& c,
                                     unsigned long long a,
                                     unsigned long long b) {
    asm("fma.rn.f32x2 %0, %1, %2, %0;" : "+l"(c) : "l"(a), "l"(b));
}
__device__ __forceinline__ unsigned long long dup2(float x) {
    unsigned long long r;
    asm("mov.b64 %0, {%1, %1};" : "=l"(r) : "f"(x));
    return r;
}
__device__ __forceinline__ float2 unpack2(unsigned long long v) {
    float2 r;
    asm("mov.b64 {%0, %1}, %2;" : "=f"(r.x), "=f"(r.y) : "l"(v));
    return r;
}

// ---------------- zero / CSR build -----------------------------------------
__global__ void zero_kernel(int n) {
    int i = blockIdx.x * blockDim.x + threadIdx.x;
    if (i <= n) g_cnt[i] = 0;
    if (i < HID) { g_colsum[i] = 0.f; g_colsq[i] = 0.f; }
}

__global__ void count_kernel(const int* __restrict__ dst, int e) {
    int i = blockIdx.x * blockDim.x + threadIdx.x;
    if (i < e) atomicAdd(&g_cnt[dst[i]], 1);
}

// block-level exclusive scan (1024-wide Hillis-Steele)
__global__ void scanA(int n) {
    __shared__ int sm[1024];
    int tid = threadIdx.x;
    int gid = blockIdx.x * 1024 + tid;
    int v = (gid < n) ? g_cnt[gid] : 0;
    sm[tid] = v;
    __syncthreads();
    for (int off = 1; off < 1024; off <<= 1) {
        int t = (tid >= off) ? sm[tid - off] : 0;
        __syncthreads();
        sm[tid] += t;
        __syncthreads();
    }
    if (gid < n) g_rowoff[gid] = sm[tid] - v;   // exclusive
    if (tid == 1023) g_blksum[blockIdx.x] = sm[1023];
}

__global__ void scanB(int nb) {
    __shared__ int sm[64];
    int tid = threadIdx.x;
    int v = (tid < nb) ? g_blksum[tid] : 0;
    sm[tid] = v;
    __syncthreads();
    for (int off = 1; off < 64; off <<= 1) {
        int t = (tid >= off) ? sm[tid - off] : 0;
        __syncthreads();
        sm[tid] += t;
        __syncthreads();
    }
    if (tid < nb) g_blksum[tid] = sm[tid] - v;  // exclusive
}

__global__ void scanC(int n, int e) {
    int gid = blockIdx.x * blockDim.x + threadIdx.x;
    if (gid < n) {
        int r = g_rowoff[gid] + g_blksum[gid >> 10];
        g_rowoff[gid] = r;
        g_cursor[gid] = r;
    }
    if (gid == 0) g_rowoff[n] = e;
}

__global__ void scatter_kernel(const int* __restrict__ src,
                               const int* __restrict__ dst, int e) {
    int i = blockIdx.x * blockDim.x + threadIdx.x;
    if (i < e) {
        int p = atomicAdd(&g_cursor[dst[i]], 1);
        g_csrc[p] = src[i];
    }
}

// ---------------- GEMM: C[M,256] = A[M,256] @ W[256,256] -------------------
// MODE 0: A = x (arg), z selects (WQ->g_Q, WK->g_K, WV->g_V)
// MODE 1: A = g_attn, W = W0 (W_out), C = g_h, epilogue += bias + resid
// Inner product uses packed fma.rn.f32x2 (2 fp32 FMA per instr on Blackwell).
template <int MODE>
__global__ void __launch_bounds__(256, 2)
gemm256(const float* __restrict__ A,
        const float* __restrict__ W0,
        const float* __restrict__ W1,
        const float* __restrict__ W2,
        const float* __restrict__ bias,
        const float* __restrict__ resid,
        int M) {
    const float* Ap;
    const float* W;
    float* C;
    if (MODE == 0) {
        Ap = A;
        if (blockIdx.z == 0)      { W = W0; C = g_Q; }
        else if (blockIdx.z == 1) { W = W1; C = g_K; }
        else                      { W = W2; C = g_V; }
    } else {
        Ap = g_attn; W = W0; C = g_h;
    }

    __shared__ __align__(16) float As[8][128];   // [k][m]
    __shared__ __align__(16) float Ws[8][128];   // [k][n]

    int tid = threadIdx.x;
    int tx = tid & 15;        // col group
    int ty = tid >> 4;        // row group
    int m0 = blockIdx.y * 128;
    int n0 = blockIdx.x * 128;

    unsigned long long c2[8][4];
#pragma unroll
    for (int i = 0; i < 8; i++)
#pragma unroll
        for (int j = 0; j < 4; j++) c2[i][j] = 0ULL;

    int arow = tid >> 1;          // 0..127
    int acol = (tid & 1) * 4;     // 0 or 4
    int am = m0 + arow;
    if (am >= M) am = M - 1;      // clamp (stores are guarded)
    int wr = tid >> 5;            // 0..7
    int wc = (tid & 31) * 4;      // 0..124

    for (int k0 = 0; k0 < HID; k0 += 8) {
        float4 av = *(const float4*)(Ap + (size_t)am * HID + k0 + acol);
        float4 wv = *(const float4*)(W + (size_t)(k0 + wr) * HID + n0 + wc);
        __syncthreads();
        As[acol + 0][arow] = av.x;
        As[acol + 1][arow] = av.y;
        As[acol + 2][arow] = av.z;
        As[acol + 3][arow] = av.w;
        *(float4*)(&Ws[wr][wc]) = wv;
        __syncthreads();
#pragma unroll
        for (int kk = 0; kk < 8; kk++) {
            float a[8];
            *(float4*)(a)     = *(const float4*)(&As[kk][ty * 8]);
            *(float4*)(a + 4) = *(const float4*)(&As[kk][ty * 8 + 4]);
            ulonglong2 b01 = *(const ulonglong2*)(&Ws[kk][tx * 8]);
            ulonglong2 b23 = *(const ulonglong2*)(&Ws[kk][tx * 8 + 4]);
            unsigned long long bb0 = b01.x, bb1 = b01.y;
            unsigned long long bb2 = b23.x, bb3 = b23.y;
#pragma unroll
            for (int i = 0; i < 8; i++) {
                unsigned long long ai = dup2(a[i]);
                fma2(c2[i][0], ai, bb0);
                fma2(c2[i][1], ai, bb1);
                fma2(c2[i][2], ai, bb2);
                fma2(c2[i][3], ai, bb3);
            }
        }
    }

#pragma unroll
    for (int i = 0; i < 8; i++) {
        int m = m0 + ty * 8 + i;
        if (m < M) {
            int col = n0 + tx * 8;
            float f[8];
#pragma unroll
            for (int j = 0; j < 4; j++) {
                float2 p = unpack2(c2[i][j]);
                f[2 * j] = p.x;
                f[2 * j + 1] = p.y;
            }
            if (MODE == 1) {
#pragma unroll
                for (int j = 0; j < 8; j++)
                    f[j] += bias[col + j] + resid[(size_t)m * HID + col + j];
            }
            float4 o0 = make_float4(f[0], f[1], f[2], f[3]);
            float4 o1 = make_float4(f[4], f[5], f[6], f[7]);
            *(float4*)(C + (size_t)m * HID + col)     = o0;
            *(float4*)(C + (size_t)m * HID + col + 4) = o1;
        }
    }
}

// ---------------- attention: warp per destination node ---------------------
// lane -> dims [8*lane, 8*lane+8) ; head = lane>>2 (4 lanes per head)
__global__ void attn_kernel(int n) {
    int gw = (blockIdx.x * blockDim.x + threadIdx.x) >> 5;
    if (gw >= n) return;
    int lane = threadIdx.x & 31;

    const float* qr = g_Q + (size_t)gw * HID + lane * 8;
    float4 q0 = *(const float4*)qr;
    float4 q1 = *(const float4*)(qr + 4);

    int beg = g_rowoff[gw];
    int end = g_rowoff[gw + 1];

    float m = -INFINITY;
    float den = 0.f;
    float acc[8];
#pragma unroll
    for (int j = 0; j < 8; j++) acc[j] = 0.f;

    for (int e = beg; e < end; ++e) {
        int s = g_csrc[e];
        const float* kr = g_K + (size_t)s * HID + lane * 8;
        const float* vr = g_V + (size_t)s * HID + lane * 8;
        float4 k0 = *(const float4*)kr;
        float4 k1 = *(const float4*)(kr + 4);
        float4 v0 = *(const float4*)vr;
        float4 v1 = *(const float4*)(vr + 4);

        float p = q0.x * k0.x + q0.y * k0.y + q0.z * k0.z + q0.w * k0.w +
                  q1.x * k1.x + q1.y * k1.y + q1.z * k1.z + q1.w * k1.w;
        p += __shfl_xor_sync(0xffffffffu, p, 1);
        p += __shfl_xor_sync(0xffffffffu, p, 2);
        float sc = p * 0.17677669529663687f;   // 1/sqrt(32)

        float nm = fmaxf(m, sc);
        float cf = __expf(m - nm);             // 0 on first edge (m=-inf)
        float pf = __expf(sc - nm);
        den = den * cf + pf;
        acc[0] = acc[0] * cf + pf * v0.x;
        acc[1] = acc[1] * cf + pf * v0.y;
        acc[2] = acc[2] * cf + pf * v0.z;
        acc[3] = acc[3] * cf + pf * v0.w;
        acc[4] = acc[4] * cf + pf * v1.x;
        acc[5] = acc[5] * cf + pf * v1.y;
        acc[6] = acc[6] * cf + pf * v1.z;
        acc[7] = acc[7] * cf + pf * v1.w;
        m = nm;
    }

    float inv = (den > 0.f) ? 1.f / den : 0.f;
    float* o = g_attn + (size_t)gw * HID + lane * 8;
    float4 o0 = make_float4(acc[0] * inv, acc[1] * inv, acc[2] * inv, acc[3] * inv);
    float4 o1 = make_float4(acc[4] * inv, acc[5] * inv, acc[6] * inv, acc[7] * inv);
    *(float4*)o = o0;
    *(float4*)(o + 4) = o1;
}

// ---------------- GraphNorm stats + apply + GELU ---------------------------
__global__ void stats_kernel(int n) {
    int c = threadIdx.x;                 // 256 threads = 256 columns
    float s = 0.f, s2 = 0.f;
    for (int r = blockIdx.x; r < n; r += gridDim.x) {
        float v = g_h[(size_t)r * HID + c];
        s += v;
        s2 += v * v;
    }
    atomicAdd(&g_colsum[c], s);
    atomicAdd(&g_colsq[c], s2);
}

__global__ void norm_gelu_kernel(const float* __restrict__ gw,
                                 const float* __restrict__ gb,
                                 const float* __restrict__ gms,
                                 float* __restrict__ out, int n) {
    int c = threadIdx.x;
    float invn = 1.f / (float)n;
    float mean = g_colsum[c] * invn;
    float ex2  = g_colsq[c] * invn;
    float s = gms[c];
    // var = E[(h - s*m)^2] = E[h^2] - 2*s*m*E[h] + s^2*m^2
    float var = ex2 - 2.f * s * mean * mean + s * s * mean * mean;
    float rstd = rsqrtf(var + 1e-5f);
    float w = gw[c] * rstd;
    float b = gb[c];
    float off = s * mean;
    for (int r = blockIdx.x; r < n; r += gridDim.x) {
        float h = g_h[(size_t)r * HID + c];
        float o = (h - off) * w + b;
        out[(size_t)r * HID + c] = 0.5f * o * (1.f + erff(o * 0.70710678118654752f));
    }
}

// ---------------- launch ----------------------------------------------------
extern "C" void kernel_launch(void* const* d_in, const int* in_sizes, int n_in,
                              void* d_out, int out_size) {
    const float* x     = (const float*)d_in[0];
    const float* WQ    = (const float*)d_in[1];
    const float* WK    = (const float*)d_in[2];
    const float* WV    = (const float*)d_in[3];
    const float* W_out = (const float*)d_in[4];
    const float* b_out = (const float*)d_in[5];
    const float* gnw   = (const float*)d_in[6];
    const float* gnb   = (const float*)d_in[7];
    const float* gms   = (const float*)d_in[8];
    const int*   ei    = (const int*)d_in[9];

    int n = in_sizes[0] / HID;
    int e = in_sizes[9] / 2;
    if (n > NMAX || e > EMAX) return;

    const int* src = ei;
    const int* dst = ei + e;

    // CSR build
    zero_kernel<<<(n + 256) / 256, 256>>>(n);
    count_kernel<<<(e + 255) / 256, 256>>>(dst, e);
    int nb = (n + 1023) / 1024;
    scanA<<<nb, 1024>>>(n);
    scanB<<<1, 64>>>(nb);
    scanC<<<(n + 255) / 256, 256>>>(n, e);
    scatter_kernel<<<(e + 255) / 256, 256>>>(src, dst, e);

    // QKV projections
    dim3 gqkv(2, (n + 127) / 128, 3);
    gemm256<0><<<gqkv, 256>>>(x, WQ, WK, WV, nullptr, nullptr, n);

    // attention (warp per node)
    attn_kernel<<<(n * 32 + 255) / 256, 256>>>(n);

    // out projection + bias + residual
    dim3 gout(2, (n + 127) / 128, 1);
    gemm256<1><<<gout, 256>>>(nullptr, W_out, nullptr, nullptr, b_out, x, n);

    // GraphNorm + GELU
    stats_kernel<<<512, 256>>>(n);
    norm_gelu_kernel<<<512, 256>>>(gnw, gnb, gms, (float*)d_out, n);
}

// round 11
// speedup vs baseline: 1.0490x; 1.0037x over previous
#include <cuda_runtime.h>
#include <cuda_bf16.h>
#include <mma.h>
#include <math.h>
#include <stdint.h>

namespace wmma = nvcuda::wmma;

#define HID 256
#define NMAX 50000
#define EMAX 800000

// ---------------- device scratch (static: no allocations allowed) ----------
__device__ float g_Q[(size_t)NMAX * HID];
__device__ float g_K[(size_t)NMAX * HID];
__device__ float g_V[(size_t)NMAX * HID];
__device__ float g_attn[(size_t)NMAX * HID];
__device__ float g_h[(size_t)NMAX * HID];

__device__ int g_cnt[NMAX + 1];
__device__ int g_rowoff[NMAX + 1];
__device__ int g_cursor[NMAX];
__device__ int g_csrc[EMAX];
__device__ int g_blksum[64];

__device__ float g_colsum[HID];
__device__ float g_colsq[HID];

// ---------------- TC probe scratch (zero-initialized by module load) -------
__device__ unsigned short g_probe_in[512];   // 2 x 16x16 bf16 tiles of zeros
__device__ float g_probe_out[256];           // never read by the pipeline

// ---------------- TC probe: minimal WMMA kernel, output unused -------------
// 1 block, 32 threads. Computes 0x0 mma on zeros, stores zeros to scratch.
// Sole purpose: determine whether ANY launched tensor-core kernel triggers
// the harness's 256MiB device-memory delta on this stack.
__global__ void tc_probe() {
    wmma::fragment<wmma::matrix_a, 16, 16, 16, __nv_bfloat16, wmma::row_major> a;
    wmma::fragment<wmma::matrix_b, 16, 16, 16, __nv_bfloat16, wmma::row_major> b;
    wmma::fragment<wmma::accumulator, 16, 16, 16, float> c;
    wmma::fill_fragment(c, 0.f);
    wmma::load_matrix_sync(a, (const __nv_bfloat16*)g_probe_in, 16);
    wmma::load_matrix_sync(b, (const __nv_bfloat16*)g_probe_in + 256, 16);
    wmma::mma_sync(c, a, b, c);
    wmma::store_matrix_sync(g_probe_out, c, 16, wmma::mem_row_major);
}

// ---------------- packed f32x2 helpers (Blackwell) -------------------------
__device__ __forceinline__ void fma2(unsigned long long& c,
                                     unsigned long long a,
                                     unsigned long long b) {
    asm("fma.rn.f32x2 %0, %1, %2, %0;" : "+l"(c) : "l"(a), "l"(b));
}
__device__ __forceinline__ unsigned long long dup2(float x) {
    unsigned long long r;
    asm("mov.b64 %0, {%1, %1};" : "=l"(r) : "f"(x));
    return r;
}
__device__ __forceinline__ float2 unpack2(unsigned long long v) {
    float2 r;
    asm("mov.b64 {%0, %1}, %2;" : "=f"(r.x), "=f"(r.y) : "l"(v));
    return r;
}

// ---------------- zero / CSR build -----------------------------------------
__global__ void zero_kernel(int n) {
    int i = blockIdx.x * blockDim.x + threadIdx.x;
    if (i <= n) g_cnt[i] = 0;
    if (i < HID) { g_colsum[i] = 0.f; g_colsq[i] = 0.f; }
}

__global__ void count_kernel(const int* __restrict__ dst, int e) {
    int i = blockIdx.x * blockDim.x + threadIdx.x;
    if (i < e) atomicAdd(&g_cnt[dst[i]], 1);
}

// block-level exclusive scan (1024-wide Hillis-Steele)
__global__ void scanA(int n) {
    __shared__ int sm[1024];
    int tid = threadIdx.x;
    int gid = blockIdx.x * 1024 + tid;
    int v = (gid < n) ? g_cnt[gid] : 0;
    sm[tid] = v;
    __syncthreads();
    for (int off = 1; off < 1024; off <<= 1) {
        int t = (tid >= off) ? sm[tid - off] : 0;
        __syncthreads();
        sm[tid] += t;
        __syncthreads();
    }
    if (gid < n) g_rowoff[gid] = sm[tid] - v;   // exclusive
    if (tid == 1023) g_blksum[blockIdx.x] = sm[1023];
}

__global__ void scanB(int nb) {
    __shared__ int sm[64];
    int tid = threadIdx.x;
    int v = (tid < nb) ? g_blksum[tid] : 0;
    sm[tid] = v;
    __syncthreads();
    for (int off = 1; off < 64; off <<= 1) {
        int t = (tid >= off) ? sm[tid - off] : 0;
        __syncthreads();
        sm[tid] += t;
        __syncthreads();
    }
    if (tid < nb) g_blksum[tid] = sm[tid] - v;  // exclusive
}

__global__ void scanC(int n, int e) {
    int gid = blockIdx.x * blockDim.x + threadIdx.x;
    if (gid < n) {
        int r = g_rowoff[gid] + g_blksum[gid >> 10];
        g_rowoff[gid] = r;
        g_cursor[gid] = r;
    }
    if (gid == 0) g_rowoff[n] = e;
}

__global__ void scatter_kernel(const int* __restrict__ src,
                               const int* __restrict__ dst, int e) {
    int i = blockIdx.x * blockDim.x + threadIdx.x;
    if (i < e) {
        int p = atomicAdd(&g_cursor[dst[i]], 1);
        g_csrc[p] = src[i];
    }
}

// ---------------- GEMM: C[M,256] = A[M,256] @ W[256,256] -------------------
// MODE 0: A = x (arg), z selects (WQ->g_Q, WK->g_K, WV->g_V)
// MODE 1: A = g_attn, W = W0 (W_out), C = g_h, epilogue += bias + resid
// Inner product uses packed fma.rn.f32x2 (2 fp32 FMA per instr on Blackwell).
template <int MODE>
__global__ void __launch_bounds__(256, 2)
gemm256(const float* __restrict__ A,
        const float* __restrict__ W0,
        const float* __restrict__ W1,
        const float* __restrict__ W2,
        const float* __restrict__ bias,
        const float* __restrict__ resid,
        int M) {
    const float* Ap;
    const float* W;
    float* C;
    if (MODE == 0) {
        Ap = A;
        if (blockIdx.z == 0)      { W = W0; C = g_Q; }
        else if (blockIdx.z == 1) { W = W1; C = g_K; }
        else                      { W = W2; C = g_V; }
    } else {
        Ap = g_attn; W = W0; C = g_h;
    }

    __shared__ __align__(16) float As[8][128];   // [k][m]
    __shared__ __align__(16) float Ws[8][128];   // [k][n]

    int tid = threadIdx.x;
    int tx = tid & 15;        // col group
    int ty = tid >> 4;        // row group
    int m0 = blockIdx.y * 128;
    int n0 = blockIdx.x * 128;

    unsigned long long c2[8][4];
#pragma unroll
    for (int i = 0; i < 8; i++)
#pragma unroll
        for (int j = 0; j < 4; j++) c2[i][j] = 0ULL;

    int arow = tid >> 1;          // 0..127
    int acol = (tid & 1) * 4;     // 0 or 4
    int am = m0 + arow;
    if (am >= M) am = M - 1;      // clamp (stores are guarded)
    int wr = tid >> 5;            // 0..7
    int wc = (tid & 31) * 4;      // 0..124

    for (int k0 = 0; k0 < HID; k0 += 8) {
        float4 av = *(const float4*)(Ap + (size_t)am * HID + k0 + acol);
        float4 wv = *(const float4*)(W + (size_t)(k0 + wr) * HID + n0 + wc);
        __syncthreads();
        As[acol + 0][arow] = av.x;
        As[acol + 1][arow] = av.y;
        As[acol + 2][arow] = av.z;
        As[acol + 3][arow] = av.w;
        *(float4*)(&Ws[wr][wc]) = wv;
        __syncthreads();
#pragma unroll
        for (int kk = 0; kk < 8; kk++) {
            float a[8];
            *(float4*)(a)     = *(const float4*)(&As[kk][ty * 8]);
            *(float4*)(a + 4) = *(const float4*)(&As[kk][ty * 8 + 4]);
            ulonglong2 b01 = *(const ulonglong2*)(&Ws[kk][tx * 8]);
            ulonglong2 b23 = *(const ulonglong2*)(&Ws[kk][tx * 8 + 4]);
            unsigned long long bb0 = b01.x, bb1 = b01.y;
            unsigned long long bb2 = b23.x, bb3 = b23.y;
#pragma unroll
            for (int i = 0; i < 8; i++) {
                unsigned long long ai = dup2(a[i]);
                fma2(c2[i][0], ai, bb0);
                fma2(c2[i][1], ai, bb1);
                fma2(c2[i][2], ai, bb2);
                fma2(c2[i][3], ai, bb3);
            }
        }
    }

#pragma unroll
    for (int i = 0; i < 8; i++) {
        int m = m0 + ty * 8 + i;
        if (m < M) {
            int col = n0 + tx * 8;
            float f[8];
#pragma unroll
            for (int j = 0; j < 4; j++) {
                float2 p = unpack2(c2[i][j]);
                f[2 * j] = p.x;
                f[2 * j + 1] = p.y;
            }
            if (MODE == 1) {
#pragma unroll
                for (int j = 0; j < 8; j++)
                    f[j] += bias[col + j] + resid[(size_t)m * HID + col + j];
            }
            float4 o0 = make_float4(f[0], f[1], f[2], f[3]);
            float4 o1 = make_float4(f[4], f[5], f[6], f[7]);
            *(float4*)(C + (size_t)m * HID + col)     = o0;
            *(float4*)(C + (size_t)m * HID + col + 4) = o1;
        }
    }
}

// ---------------- attention: warp per destination node ---------------------
// lane -> dims [8*lane, 8*lane+8) ; head = lane>>2 (4 lanes per head)
__global__ void attn_kernel(int n) {
    int gw = (blockIdx.x * blockDim.x + threadIdx.x) >> 5;
    if (gw >= n) return;
    int lane = threadIdx.x & 31;

    const float* qr = g_Q + (size_t)gw * HID + lane * 8;
    float4 q0 = *(const float4*)qr;
    float4 q1 = *(const float4*)(qr + 4);

    int beg = g_rowoff[gw];
    int end = g_rowoff[gw + 1];

    float m = -INFINITY;
    float den = 0.f;
    float acc[8];
#pragma unroll
    for (int j = 0; j < 8; j++) acc[j] = 0.f;

    for (int e = beg; e < end; ++e) {
        int s = g_csrc[e];
        const float* kr = g_K + (size_t)s * HID + lane * 8;
        const float* vr = g_V + (size_t)s * HID + lane * 8;
        float4 k0 = *(const float4*)kr;
        float4 k1 = *(const float4*)(kr + 4);
        float4 v0 = *(const float4*)vr;
        float4 v1 = *(const float4*)(vr + 4);

        float p = q0.x * k0.x + q0.y * k0.y + q0.z * k0.z + q0.w * k0.w +
                  q1.x * k1.x + q1.y * k1.y + q1.z * k1.z + q1.w * k1.w;
        p += __shfl_xor_sync(0xffffffffu, p, 1);
        p += __shfl_xor_sync(0xffffffffu, p, 2);
        float sc = p * 0.17677669529663687f;   // 1/sqrt(32)

        float nm = fmaxf(m, sc);
        float cf = __expf(m - nm);             // 0 on first edge (m=-inf)
        float pf = __expf(sc - nm);
        den = den * cf + pf;
        acc[0] = acc[0] * cf + pf * v0.x;
        acc[1] = acc[1] * cf + pf * v0.y;
        acc[2] = acc[2] * cf + pf * v0.z;
        acc[3] = acc[3] * cf + pf * v0.w;
        acc[4] = acc[4] * cf + pf * v1.x;
        acc[5] = acc[5] * cf + pf * v1.y;
        acc[6] = acc[6] * cf + pf * v1.z;
        acc[7] = acc[7] * cf + pf * v1.w;
        m = nm;
    }

    float inv = (den > 0.f) ? 1.f / den : 0.f;
    float* o = g_attn + (size_t)gw * HID + lane * 8;
    float4 o0 = make_float4(acc[0] * inv, acc[1] * inv, acc[2] * inv, acc[3] * inv);
    float4 o1 = make_float4(acc[4] * inv, acc[5] * inv, acc[6] * inv, acc[7] * inv);
    *(float4*)o = o0;
    *(float4*)(o + 4) = o1;
}

// ---------------- GraphNorm stats + apply + GELU ---------------------------
__global__ void stats_kernel(int n) {
    int c = threadIdx.x;                 // 256 threads = 256 columns
    float s = 0.f, s2 = 0.f;
    for (int r = blockIdx.x; r < n; r += gridDim.x) {
        float v = g_h[(size_t)r * HID + c];
        s += v;
        s2 += v * v;
    }
    atomicAdd(&g_colsum[c], s);
    atomicAdd(&g_colsq[c], s2);
}

__global__ void norm_gelu_kernel(const float* __restrict__ gw,
                                 const float* __restrict__ gb,
                                 const float* __restrict__ gms,
                                 float* __restrict__ out, int n) {
    int c = threadIdx.x;
    float invn = 1.f / (float)n;
    float mean = g_colsum[c] * invn;
    float ex2  = g_colsq[c] * invn;
    float s = gms[c];
    // var = E[(h - s*m)^2] = E[h^2] - 2*s*m*E[h] + s^2*m^2
    float var = ex2 - 2.f * s * mean * mean + s * s * mean * mean;
    float rstd = rsqrtf(var + 1e-5f);
    float w = gw[c] * rstd;
    float b = gb[c];
    float off = s * mean;
    for (int r = blockIdx.x; r < n; r += gridDim.x) {
        float h = g_h[(size_t)r * HID + c];
        float o = (h - off) * w + b;
        out[(size_t)r * HID + c] = 0.5f * o * (1.f + erff(o * 0.70710678118654752f));
    }
}

// ---------------- launch ----------------------------------------------------
extern "C" void kernel_launch(void* const* d_in, const int* in_sizes, int n_in,
                              void* d_out, int out_size) {
    const float* x     = (const float*)d_in[0];
    const float* WQ    = (const float*)d_in[1];
    const float* WK    = (const float*)d_in[2];
    const float* WV    = (const float*)d_in[3];
    const float* W_out = (const float*)d_in[4];
    const float* b_out = (const float*)d_in[5];
    const float* gnw   = (const float*)d_in[6];
    const float* gnb   = (const float*)d_in[7];
    const float* gms   = (const float*)d_in[8];
    const int*   ei    = (const int*)d_in[9];

    int n = in_sizes[0] / HID;
    int e = in_sizes[9] / 2;
    if (n > NMAX || e > EMAX) return;

    const int* src = ei;
    const int* dst = ei + e;

    // TC probe: 1 warp, zeros -> unused scratch. Bisects the 256MiB mystery.
    tc_probe<<<1, 32>>>();

    // CSR build
    zero_kernel<<<(n + 256) / 256, 256>>>(n);
    count_kernel<<<(e + 255) / 256, 256>>>(dst, e);
    int nb = (n + 1023) / 1024;
    scanA<<<nb, 1024>>>(n);
    scanB<<<1, 64>>>(nb);
    scanC<<<(n + 255) / 256, 256>>>(n, e);
    scatter_kernel<<<(e + 255) / 256, 256>>>(src, dst, e);

    // QKV projections
    dim3 gqkv(2, (n + 127) / 128, 3);
    gemm256<0><<<gqkv, 256>>>(x, WQ, WK, WV, nullptr, nullptr, n);

    // attention (warp per node)
    attn_kernel<<<(n * 32 + 255) / 256, 256>>>(n);

    // out projection + bias + residual
    dim3 gout(2, (n + 127) / 128, 1);
    gemm256<1><<<gout, 256>>>(nullptr, W_out, nullptr, nullptr, b_out, x, n);

    // GraphNorm + GELU
    stats_kernel<<<512, 256>>>(n);
    norm_gelu_kernel<<<512, 256>>>(gnw, gnb, gms, (float*)d_out, n);
}